// round 1
// baseline (speedup 1.0000x reference)
#include <cuda_runtime.h>
#include <math.h>

// NT-Xent loss, B=4096, D=128, N=8192, T=0.5
// Phase 1: normalize rows of [z_i; z_j] -> g_zn, zero g_rowsum
// Phase 2: tiled Zn x Zn^T with online exp-accumulation (no NxN materialization)
// Phase 3: loss = mean(-pos + log(rowsum))

#define NB     4096
#define DD     128
#define NN     8192
#define TM     128
#define TN     128
#define NSPLIT 2        // 2-way column split -> 128 blocks; 2-way atomic add is commutative => deterministic
#define SDIM   132      // padded row stride (k-major smem) to break STS bank conflicts

__device__ float g_zn[NN * DD];
__device__ float g_rowsum[NN];
__device__ float g_pos[NN];

// Pure fixed-latency exp (no MUFU): exp(x)=2^(x*log2e), magic-number round,
// degree-6 poly for 2^f on [-0.5,0.5]. |err| ~1e-7 rel. Valid for |x| <= ~60.
__device__ __forceinline__ float fexp(float x) {
    const float L2E = 1.4426950408889634f;
    float t  = fmaf(x, L2E, 12582912.0f);          // 1.5*2^23 magic: round to nearest int
    int   ei = __float_as_int(t) - 0x4B400000;     // integer part n
    float fi = t - 12582912.0f;                    // (float)n
    float f  = fmaf(x, L2E, -fi);                  // frac in [-0.5, 0.5]
    float p  =        1.54035304e-4f;
    p = fmaf(p, f, 1.33335581e-3f);
    p = fmaf(p, f, 9.61812911e-3f);
    p = fmaf(p, f, 5.55041087e-2f);
    p = fmaf(p, f, 2.40226507e-1f);
    p = fmaf(p, f, 6.93147181e-1f);
    p = fmaf(p, f, 1.0f);
    return __int_as_float((ei + 127) << 23) * p;   // 2^n * 2^f
}

// One block per row (128 threads = D). Also zeroes g_rowsum for this row.
__global__ void knorm(const float* __restrict__ zi, const float* __restrict__ zj) {
    int r = blockIdx.x;
    int t = threadIdx.x;
    const float* src = (r < NB) ? (zi + (size_t)r * DD) : (zj + (size_t)(r - NB) * DD);
    float x = src[t];
    float s = x * x;
    #pragma unroll
    for (int o = 16; o > 0; o >>= 1) s += __shfl_xor_sync(0xffffffffu, s, o);
    __shared__ float ws[4];
    if ((t & 31) == 0) ws[t >> 5] = s;
    __syncthreads();
    float tot = ws[0] + ws[1] + ws[2] + ws[3];
    float scale = 1.0f / fmaxf(sqrtf(tot), 1e-12f);   // matches F.normalize eps
    g_zn[(size_t)r * DD + t] = x * scale;
    if (t == 0) g_rowsum[r] = 0.0f;
}

// Main contraction. Grid (NN/TM, NSPLIT), 256 threads, 8x8 microtile.
// Smem tiles stored k-major (As[k][row], Bs[k][col]) for conflict-free float4
// reads in the FMA loop; fill mapping gives 8x64B global segments per warp and
// ~2-way STS conflicts (padded stride 132).
__global__ void __launch_bounds__(256, 1) kmain() {
    extern __shared__ float sm[];
    float* As = sm;                  // [DD][SDIM]
    float* Bs = sm + DD * SDIM;      // [DD][SDIM]
    int tid = threadIdx.x;
    int tx = tid & 15, ty = tid >> 4;
    int r0 = blockIdx.x * TM;
    int split = blockIdx.y;

    // Fill A (row tile, reused across all column tiles)
    for (int idx = tid; idx < TM * (DD / 4); idx += 256) {
        int col = (idx & 7) | ((idx >> 5) & 0x78);   // tile row
        int kc  = (idx >> 3) & 31;                   // float4 index along D
        float4 v = ((const float4*)g_zn)[(size_t)(r0 + col) * (DD / 4) + kc];
        As[(4 * kc + 0) * SDIM + col] = v.x;
        As[(4 * kc + 1) * SDIM + col] = v.y;
        As[(4 * kc + 2) * SDIM + col] = v.z;
        As[(4 * kc + 3) * SDIM + col] = v.w;
    }

    float rs[8];
    #pragma unroll
    for (int i = 0; i < 8; i++) rs[i] = 0.0f;

    const int tiles = (NN / NSPLIT) / TN;   // 32
    for (int tt = 0; tt < tiles; ++tt) {
        int c0 = split * (NN / NSPLIT) + tt * TN;
        __syncthreads();                     // prev compute done before refill
        for (int idx = tid; idx < TN * (DD / 4); idx += 256) {
            int col = (idx & 7) | ((idx >> 5) & 0x78);
            int kc  = (idx >> 3) & 31;
            float4 v = ((const float4*)g_zn)[(size_t)(c0 + col) * (DD / 4) + kc];
            Bs[(4 * kc + 0) * SDIM + col] = v.x;
            Bs[(4 * kc + 1) * SDIM + col] = v.y;
            Bs[(4 * kc + 2) * SDIM + col] = v.z;
            Bs[(4 * kc + 3) * SDIM + col] = v.w;
        }
        __syncthreads();

        float acc[8][8];
        #pragma unroll
        for (int i = 0; i < 8; i++)
            #pragma unroll
            for (int j = 0; j < 8; j++) acc[i][j] = 0.0f;

        #pragma unroll 8
        for (int k = 0; k < DD; ++k) {
            float4 a0 = *(const float4*)&As[k * SDIM + ty * 8];
            float4 a1 = *(const float4*)&As[k * SDIM + ty * 8 + 4];
            float4 b0 = *(const float4*)&Bs[k * SDIM + tx * 8];
            float4 b1 = *(const float4*)&Bs[k * SDIM + tx * 8 + 4];
            float av[8] = {a0.x, a0.y, a0.z, a0.w, a1.x, a1.y, a1.z, a1.w};
            float bv[8] = {b0.x, b0.y, b0.z, b0.w, b1.x, b1.y, b1.z, b1.w};
            #pragma unroll
            for (int i = 0; i < 8; i++)
                #pragma unroll
                for (int j = 0; j < 8; j++)
                    acc[i][j] = fmaf(av[i], bv[j], acc[i][j]);
        }

        bool dt = (c0 == r0);                          // tile contains the diagonal
        bool pt = (c0 == ((r0 + NB) & (NN - 1)));      // tile contains the positives
        bool dg = (tx == ty);                          // microtile on tile diagonal
        #pragma unroll
        for (int i = 0; i < 8; i++) {
            #pragma unroll
            for (int j = 0; j < 8; j++) {
                float s = acc[i][j] * 2.0f;            // 1/TEMPERATURE
                float e = fexp(s);
                bool self = dg && (i == j);
                if (!(dt && self)) rs[i] += e;         // exclude self from lse
                if (pt && self) g_pos[r0 + ty * 8 + i] = s;  // record positive sim
            }
        }
    }

    __syncthreads();
    // Reduce row sums across the 16 tx threads sharing each row (reuse smem)
    #pragma unroll
    for (int i = 0; i < 8; i++) sm[(ty * 8 + i) * 16 + tx] = rs[i];
    __syncthreads();
    if (tid < TM) {
        float s = 0.0f;
        #pragma unroll
        for (int j = 0; j < 16; j++) s += sm[tid * 16 + j];
        atomicAdd(&g_rowsum[r0 + tid], s);   // exactly NSPLIT=2 adds per row: commutative => deterministic
    }
}

__global__ void kfin(float* __restrict__ out) {
    int t = threadIdx.x;
    float a = 0.0f;
    for (int i = t; i < NN; i += 256)
        a += logf(g_rowsum[i]) - g_pos[i];
    #pragma unroll
    for (int o = 16; o > 0; o >>= 1) a += __shfl_xor_sync(0xffffffffu, a, o);
    __shared__ float ws[8];
    if ((t & 31) == 0) ws[t >> 5] = a;
    __syncthreads();
    if (t == 0) {
        float s = 0.0f;
        #pragma unroll
        for (int w = 0; w < 8; w++) s += ws[w];
        out[0] = s / (float)NN;
    }
}

extern "C" void kernel_launch(void* const* d_in, const int* in_sizes, int n_in,
                              void* d_out, int out_size) {
    const float* zi = (const float*)d_in[0];
    const float* zj = (const float*)d_in[1];
    float* out = (float*)d_out;

    (void)in_sizes; (void)n_in; (void)out_size;

    const int smem_bytes = 2 * DD * SDIM * (int)sizeof(float);   // 132 KB
    cudaFuncSetAttribute(kmain, cudaFuncAttributeMaxDynamicSharedMemorySize, smem_bytes);

    knorm<<<NN, DD>>>(zi, zj);
    dim3 grid(NN / TM, NSPLIT);
    kmain<<<grid, 256, smem_bytes>>>();
    kfin<<<1, 256>>>(out);
}

// round 8
// speedup vs baseline: 1.5141x; 1.5141x over previous
#include <cuda_runtime.h>
#include <mma.h>
#include <math.h>

using namespace nvcuda;

// NT-Xent loss, B=4096, D=128, N=8192, T=0.5
// tf32 WMMA contraction of sim = Zn·Zn^T, online exp accumulation in registers.

#define NB     4096
#define DD     128
#define NN     8192
#define TM     128
#define TN     64
#define NSPLIT 2
#define CTILES ((NN / NSPLIT) / TN)   // 64
#define LDA    132                    // padded smem leading dim (floats)
#define LDC    36                     // padded C scratch leading dim (floats)

// smem layout (floats): As[128*132] | Bs[2][64*132] | Cs[8][32*36]
#define AS_OFF 0
#define BS_OFF (TM * LDA)
#define CS_OFF (BS_OFF + 2 * TN * LDA)
#define SMEM_FLOATS (CS_OFF + 8 * 32 * LDC)
#define SMEM_BYTES  (SMEM_FLOATS * 4)     // 172032

__device__ float g_zn[NN * DD];      // tf32-rounded normalized rows
__device__ float g_rowsum[NN];
__device__ float g_pos[NN];          // 2 * (z_r . z_pair)
__device__ float g_self[NN];         // 2 * (z_r . z_r)

// exp(2*c) = 2^(c*K), K = 2*log2(e); pure FMA/ALU, no MUFU.
// deg-4 poly for 2^f on [-0.5, 0.5], rel err ~4e-5. Valid |2c| <= ~8 here.
__device__ __forceinline__ float eterm(float c) {
    const float K     = 2.885390081777927f;   // 2/ln(2)
    const float MAGIC = 12582912.0f;          // 1.5 * 2^23
    float tt = fmaf(c, K, MAGIC);
    float fi = tt - MAGIC;
    float f  = fmaf(c, K, -fi);
    int   ei = __float_as_int(tt) - 0x4B400000;
    float sc = __int_as_float((ei + 127) << 23);
    float p  = fmaf(fmaf(fmaf(fmaf(9.6181291e-3f, f, 5.5504109e-2f), f,
                              2.4022651e-1f), f, 6.9314718e-1f), f, 1.0f);
    return p * sc;
}

// Normalize rows of [z_i; z_j], round to tf32, zero rowsum.
__global__ void knorm(const float* __restrict__ zi, const float* __restrict__ zj) {
    int r = blockIdx.x;
    int t = threadIdx.x;
    const float* src = (r < NB) ? (zi + (size_t)r * DD) : (zj + (size_t)(r - NB) * DD);
    float x = src[t];
    float s = x * x;
    #pragma unroll
    for (int o = 16; o > 0; o >>= 1) s += __shfl_xor_sync(0xffffffffu, s, o);
    __shared__ float ws[4];
    if ((t & 31) == 0) ws[t >> 5] = s;
    __syncthreads();
    float tot = ws[0] + ws[1] + ws[2] + ws[3];
    float scale = 1.0f / fmaxf(sqrtf(tot), 1e-12f);   // matches F.normalize eps
    g_zn[(size_t)r * DD + t] = wmma::__float_to_tf32(x * scale);
    if (t == 0) g_rowsum[r] = 0.0f;
}

// Positive-pair sims and self sims, in fp32 on the tf32-rounded data.
__global__ void kpos() {
    int r = blockIdx.x;          // 0..NB-1
    int t = threadIdx.x;         // 128
    float a = g_zn[(size_t)r * DD + t];
    float b = g_zn[(size_t)(r + NB) * DD + t];
    float ab = a * b, aa = a * a, bb = b * b;
    #pragma unroll
    for (int o = 16; o > 0; o >>= 1) {
        ab += __shfl_xor_sync(0xffffffffu, ab, o);
        aa += __shfl_xor_sync(0xffffffffu, aa, o);
        bb += __shfl_xor_sync(0xffffffffu, bb, o);
    }
    __shared__ float s[12];
    int w = t >> 5;
    if ((t & 31) == 0) { s[w] = ab; s[4 + w] = aa; s[8 + w] = bb; }
    __syncthreads();
    if (t == 0) {
        float AB = s[0] + s[1] + s[2] + s[3];
        float AA = s[4] + s[5] + s[6] + s[7];
        float BB = s[8] + s[9] + s[10] + s[11];
        g_pos[r]       = 2.0f * AB;
        g_pos[r + NB]  = 2.0f * AB;
        g_self[r]      = 2.0f * AA;
        g_self[r + NB] = 2.0f * BB;
    }
}

// Main contraction. Grid (NN/TM, NSPLIT), 256 threads (8 warps, 4x2 warp grid).
__global__ void __launch_bounds__(256, 1) kmain() {
    extern __shared__ float sm[];
    float* As  = sm + AS_OFF;
    float* Bs0 = sm + BS_OFF;
    float* Bs1 = sm + BS_OFF + TN * LDA;
    const int tid = threadIdx.x;
    const int wid = tid >> 5, lid = tid & 31;
    const int wr = wid >> 1, wc = wid & 1;       // warp row-group (0..3), col-group (0..1)
    const int r0 = blockIdx.x * TM;
    const int cb = blockIdx.y * (NN / NSPLIT);
    float* Cw = sm + CS_OFF + wid * 32 * LDC;    // per-warp 32x32 (pad 36) scratch

    // Load A tile (128 rows, resident all iterations)
    for (int i = tid; i < TM * 32; i += 256) {
        int row = i >> 5, c4 = i & 31;
        float4 v = ((const float4*)g_zn)[(size_t)(r0 + row) * 32 + c4];
        float* d = &As[row * LDA + c4 * 4];
        d[0] = v.x; d[1] = v.y; d[2] = v.z; d[3] = v.w;
    }
    // Load B tile 0
    for (int i = tid; i < TN * 32; i += 256) {
        int row = i >> 5, c4 = i & 31;
        float4 v = ((const float4*)g_zn)[(size_t)(cb + row) * 32 + c4];
        float* d = &Bs0[row * LDA + c4 * 4];
        d[0] = v.x; d[1] = v.y; d[2] = v.z; d[3] = v.w;
    }
    __syncthreads();

    float rs = 0.0f;

    wmma::fragment<wmma::accumulator, 16, 16, 8, float> c00, c01, c10, c11;
    wmma::fragment<wmma::matrix_a, 16, 16, 8, wmma::precision::tf32, wmma::row_major> a0, a1;
    wmma::fragment<wmma::matrix_b, 16, 16, 8, wmma::precision::tf32, wmma::col_major> b0, b1;

    for (int t = 0; t < CTILES; ++t) {
        float* Bc = (t & 1) ? Bs1 : Bs0;     // current tile
        float* Bn = (t & 1) ? Bs0 : Bs1;     // next tile buffer (free since t-1 done)

        // Prefetch next B tile into registers (overlaps with MMA below)
        float4 pre0, pre1, pre2, pre3, pre4, pre5, pre6, pre7;
        if (t + 1 < CTILES) {
            const float4* src = (const float4*)g_zn + (size_t)(cb + (t + 1) * TN) * 32;
            pre0 = src[tid];        pre1 = src[tid + 256];
            pre2 = src[tid + 512];  pre3 = src[tid + 768];
            pre4 = src[tid + 1024]; pre5 = src[tid + 1280];
            pre6 = src[tid + 1536]; pre7 = src[tid + 1792];
        }

        wmma::fill_fragment(c00, 0.0f);
        wmma::fill_fragment(c01, 0.0f);
        wmma::fill_fragment(c10, 0.0f);
        wmma::fill_fragment(c11, 0.0f);

        const float* Ab = &As[(wr * 32) * LDA];
        const float* Bb = &Bc[(wc * 32) * LDA];
        #pragma unroll
        for (int ks = 0; ks < 16; ks++) {
            int k = ks * 8;
            wmma::load_matrix_sync(a0, Ab + k, LDA);
            wmma::load_matrix_sync(a1, Ab + 16 * LDA + k, LDA);
            wmma::load_matrix_sync(b0, Bb + k, LDA);
            wmma::load_matrix_sync(b1, Bb + 16 * LDA + k, LDA);
            wmma::mma_sync(c00, a0, b0, c00);
            wmma::mma_sync(c01, a0, b1, c01);
            wmma::mma_sync(c10, a1, b0, c10);
            wmma::mma_sync(c11, a1, b1, c11);
        }

        // Stage C through per-warp smem scratch, then branch-free exp accumulation.
        wmma::store_matrix_sync(Cw,                 c00, LDC, wmma::mem_row_major);
        wmma::store_matrix_sync(Cw + 16,            c01, LDC, wmma::mem_row_major);
        wmma::store_matrix_sync(Cw + 16 * LDC,      c10, LDC, wmma::mem_row_major);
        wmma::store_matrix_sync(Cw + 16 * LDC + 16, c11, LDC, wmma::mem_row_major);
        __syncwarp();
        {
            const float* crow = &Cw[lid * LDC];   // lane owns one row, 32 cols
            #pragma unroll
            for (int c4 = 0; c4 < 8; c4++) {
                float4 v = *(const float4*)&crow[c4 * 4];
                rs += eterm(v.x);
                rs += eterm(v.y);
                rs += eterm(v.z);
                rs += eterm(v.w);
            }
        }
        __syncwarp();

        // Commit prefetched tile to the free buffer (other warps may still MMA on Bc — safe)
        if (t + 1 < CTILES) {
            float* d0 = &Bn[((tid) >> 5) * LDA + (tid & 31) * 4];
            d0[0] = pre0.x; d0[1] = pre0.y; d0[2] = pre0.z; d0[3] = pre0.w;
            float* d1 = &Bn[((tid + 256) >> 5) * LDA + (tid & 31) * 4];
            d1[0] = pre1.x; d1[1] = pre1.y; d1[2] = pre1.z; d1[3] = pre1.w;
            float* d2 = &Bn[((tid + 512) >> 5) * LDA + (tid & 31) * 4];
            d2[0] = pre2.x; d2[1] = pre2.y; d2[2] = pre2.z; d2[3] = pre2.w;
            float* d3 = &Bn[((tid + 768) >> 5) * LDA + (tid & 31) * 4];
            d3[0] = pre3.x; d3[1] = pre3.y; d3[2] = pre3.z; d3[3] = pre3.w;
            float* d4 = &Bn[((tid + 1024) >> 5) * LDA + (tid & 31) * 4];
            d4[0] = pre4.x; d4[1] = pre4.y; d4[2] = pre4.z; d4[3] = pre4.w;
            float* d5 = &Bn[((tid + 1280) >> 5) * LDA + (tid & 31) * 4];
            d5[0] = pre5.x; d5[1] = pre5.y; d5[2] = pre5.z; d5[3] = pre5.w;
            float* d6 = &Bn[((tid + 1536) >> 5) * LDA + (tid & 31) * 4];
            d6[0] = pre6.x; d6[1] = pre6.y; d6[2] = pre6.z; d6[3] = pre6.w;
            float* d7 = &Bn[((tid + 1792) >> 5) * LDA + (tid & 31) * 4];
            d7[0] = pre7.x; d7[1] = pre7.y; d7[2] = pre7.z; d7[3] = pre7.w;
        }
        __syncthreads();   // Bn complete + all warps done with this iteration
    }

    // Reduce the two col-group warps per row, then 2 commutative atomics per row.
    float* red = sm;   // As no longer needed
    red[(wr * 32 + lid) * 2 + wc] = rs;
    __syncthreads();
    if (tid < TM)
        atomicAdd(&g_rowsum[r0 + tid], red[tid * 2] + red[tid * 2 + 1]);
}

// loss = mean( log(rowsum - exp(self)) - pos )
__global__ void kfin(float* __restrict__ out) {
    int t = threadIdx.x;
    float a = 0.0f;
    for (int i = t; i < NN; i += 256)
        a += logf(g_rowsum[i] - expf(g_self[i])) - g_pos[i];
    #pragma unroll
    for (int o = 16; o > 0; o >>= 1) a += __shfl_xor_sync(0xffffffffu, a, o);
    __shared__ float ws[8];
    if ((t & 31) == 0) ws[t >> 5] = a;
    __syncthreads();
    if (t == 0) {
        float s = 0.0f;
        #pragma unroll
        for (int w = 0; w < 8; w++) s += ws[w];
        out[0] = s / (float)NN;
    }
}

extern "C" void kernel_launch(void* const* d_in, const int* in_sizes, int n_in,
                              void* d_out, int out_size) {
    const float* zi = (const float*)d_in[0];
    const float* zj = (const float*)d_in[1];
    float* out = (float*)d_out;
    (void)in_sizes; (void)n_in; (void)out_size;

    cudaFuncSetAttribute(kmain, cudaFuncAttributeMaxDynamicSharedMemorySize, SMEM_BYTES);

    knorm<<<NN, DD>>>(zi, zj);
    kpos<<<NB, DD>>>();
    dim3 grid(NN / TM, NSPLIT);
    kmain<<<grid, 256, SMEM_BYTES>>>();
    kfin<<<1, 256>>>(out);
}

// round 11
// speedup vs baseline: 1.7198x; 1.1359x over previous
#include <cuda_runtime.h>
#include <mma.h>
#include <math.h>

using namespace nvcuda;

// NT-Xent loss, B=4096, D=128, N=8192, T=0.5
// tf32 WMMA contraction, register-resident online exp epilogue.

#define NB     4096
#define DD     128
#define NN     8192
#define TM     128
#define TN     128
#define NSPLIT 2
#define CTILES ((NN / NSPLIT) / TN)   // 32
#define LDA    132                    // padded smem leading dim (floats)

// smem layout (floats): As[128*132] | Bs[2][128*132]; reduce scratch reuses As.
#define AS_OFF 0
#define BS_OFF (TM * LDA)
#define SMEM_FLOATS (BS_OFF + 2 * TN * LDA)
#define SMEM_BYTES  (SMEM_FLOATS * 4)     // 202752

__device__ float g_zn[NN * DD];      // tf32-rounded normalized rows
__device__ float g_rowsum[NN];
__device__ float g_pos[NN];          // 2 * (z_r . z_pair)
__device__ float g_self[NN];         // 2 * (z_r . z_r)

// exp(2*c) = 2^(c*K), K = 2*log2(e); pure FMA/ALU, no MUFU.
__device__ __forceinline__ float eterm(float c) {
    const float K     = 2.885390081777927f;   // 2/ln(2)
    const float MAGIC = 12582912.0f;          // 1.5 * 2^23
    float tt = fmaf(c, K, MAGIC);
    float fi = tt - MAGIC;
    float f  = fmaf(c, K, -fi);
    int   ei = __float_as_int(tt) - 0x4B400000;
    float sc = __int_as_float((ei + 127) << 23);
    float p  = fmaf(fmaf(fmaf(fmaf(9.6181291e-3f, f, 5.5504109e-2f), f,
                              2.4022651e-1f), f, 6.9314718e-1f), f, 1.0f);
    return p * sc;
}

// Fused: normalize rows r and r+NB, tf32-round, store; pos/self sims; zero rowsums.
__global__ void kprep(const float* __restrict__ zi, const float* __restrict__ zj) {
    int r = blockIdx.x;          // 0..NB-1
    int t = threadIdx.x;         // 128
    int w = t >> 5;
    float xi = zi[(size_t)r * DD + t];
    float xj = zj[(size_t)r * DD + t];
    float si = xi * xi, sj = xj * xj;
    #pragma unroll
    for (int o = 16; o > 0; o >>= 1) {
        si += __shfl_xor_sync(0xffffffffu, si, o);
        sj += __shfl_xor_sync(0xffffffffu, sj, o);
    }
    __shared__ float ws[12];
    if ((t & 31) == 0) { ws[w] = si; ws[4 + w] = sj; }
    __syncthreads();
    float ti = ws[0] + ws[1] + ws[2] + ws[3];
    float tj = ws[4] + ws[5] + ws[6] + ws[7];
    float sci = 1.0f / fmaxf(sqrtf(ti), 1e-12f);   // matches F.normalize eps
    float scj = 1.0f / fmaxf(sqrtf(tj), 1e-12f);
    float a = wmma::__float_to_tf32(xi * sci);
    float b = wmma::__float_to_tf32(xj * scj);
    g_zn[(size_t)r * DD + t]        = a;
    g_zn[(size_t)(r + NB) * DD + t] = b;
    // pos/self on the tf32-rounded values (matches the GEMM)
    float ab = a * b, aa = a * a, bb = b * b;
    #pragma unroll
    for (int o = 16; o > 0; o >>= 1) {
        ab += __shfl_xor_sync(0xffffffffu, ab, o);
        aa += __shfl_xor_sync(0xffffffffu, aa, o);
        bb += __shfl_xor_sync(0xffffffffu, bb, o);
    }
    __syncthreads();
    if ((t & 31) == 0) { ws[w] = ab; ws[4 + w] = aa; ws[8 + w] = bb; }
    __syncthreads();
    if (t == 0) {
        float AB = ws[0] + ws[1] + ws[2] + ws[3];
        float AA = ws[4] + ws[5] + ws[6] + ws[7];
        float BB = ws[8] + ws[9] + ws[10] + ws[11];
        g_pos[r]       = 2.0f * AB;
        g_pos[r + NB]  = 2.0f * AB;
        g_self[r]      = 2.0f * AA;
        g_self[r + NB] = 2.0f * BB;
        g_rowsum[r] = 0.0f;
        g_rowsum[r + NB] = 0.0f;
    }
}

// Main contraction. Grid (NN/TM, NSPLIT), 256 threads (8 warps, 4x2 warp grid,
// warp tile 32x64: 2 A-frags x 4 B-frags -> 8 C-frags).
__global__ void __launch_bounds__(256, 1) kmain() {
    extern __shared__ float sm[];
    float* As  = sm + AS_OFF;
    float* Bs0 = sm + BS_OFF;
    float* Bs1 = sm + BS_OFF + TN * LDA;
    const int tid = threadIdx.x;
    const int wid = tid >> 5, lid = tid & 31;
    const int wr = wid >> 1, wc = wid & 1;       // warp row-group (0..3), col-group (0..1)
    const int r0 = blockIdx.x * TM;
    const int cb = blockIdx.y * (NN / NSPLIT);

    // Load A tile (resident) and B tile 0
    for (int i = tid; i < TM * 32; i += 256) {
        int row = i >> 5, c4 = i & 31;
        float4 v = ((const float4*)g_zn)[(size_t)(r0 + row) * 32 + c4];
        float* d = &As[row * LDA + c4 * 4];
        d[0] = v.x; d[1] = v.y; d[2] = v.z; d[3] = v.w;
    }
    for (int i = tid; i < TN * 32; i += 256) {
        int row = i >> 5, c4 = i & 31;
        float4 v = ((const float4*)g_zn)[(size_t)(cb + row) * 32 + c4];
        float* d = &Bs0[row * LDA + c4 * 4];
        d[0] = v.x; d[1] = v.y; d[2] = v.z; d[3] = v.w;
    }
    __syncthreads();

    // Per-thread row-sum accumulators: rows wr*32 + mi*16 + (lid>>2) + hi*8
    float rs00 = 0.0f, rs01 = 0.0f, rs10 = 0.0f, rs11 = 0.0f;

    wmma::fragment<wmma::accumulator, 16, 16, 8, float> cf[2][4];
    wmma::fragment<wmma::matrix_a, 16, 16, 8, wmma::precision::tf32, wmma::row_major> af[2];
    wmma::fragment<wmma::matrix_b, 16, 16, 8, wmma::precision::tf32, wmma::col_major> bf[4];

    for (int t = 0; t < CTILES; ++t) {
        float* Bc = (t & 1) ? Bs1 : Bs0;
        float* Bn = (t & 1) ? Bs0 : Bs1;

        // Prefetch next B tile into registers (16 float4/thread)
        float4 pre[16];
        if (t + 1 < CTILES) {
            const float4* src = (const float4*)g_zn + (size_t)(cb + (t + 1) * TN) * 32;
            #pragma unroll
            for (int j = 0; j < 16; j++) pre[j] = src[tid + j * 256];
        }

        #pragma unroll
        for (int mi = 0; mi < 2; mi++)
            #pragma unroll
            for (int ni = 0; ni < 4; ni++)
                wmma::fill_fragment(cf[mi][ni], 0.0f);

        const float* Ab = &As[(wr * 32) * LDA];
        const float* Bb = &Bc[(wc * 64) * LDA];
        #pragma unroll
        for (int ks = 0; ks < 16; ks++) {
            int k = ks * 8;
            #pragma unroll
            for (int mi = 0; mi < 2; mi++)
                wmma::load_matrix_sync(af[mi], Ab + mi * 16 * LDA + k, LDA);
            #pragma unroll
            for (int ni = 0; ni < 4; ni++)
                wmma::load_matrix_sync(bf[ni], Bb + ni * 16 * LDA + k, LDA);
            #pragma unroll
            for (int mi = 0; mi < 2; mi++)
                #pragma unroll
                for (int ni = 0; ni < 4; ni++)
                    wmma::mma_sync(cf[mi][ni], af[mi], bf[ni], cf[mi][ni]);
        }

        // Register epilogue. m16n16k8 f32 acc: elems {0,1,4,5} -> row lane>>2,
        // {2,3,6,7} -> row (lane>>2)+8. Columns irrelevant for row sums.
        #pragma unroll
        for (int ni = 0; ni < 4; ni++) {
            rs00 += eterm(cf[0][ni].x[0]) + eterm(cf[0][ni].x[1])
                  + eterm(cf[0][ni].x[4]) + eterm(cf[0][ni].x[5]);
            rs01 += eterm(cf[0][ni].x[2]) + eterm(cf[0][ni].x[3])
                  + eterm(cf[0][ni].x[6]) + eterm(cf[0][ni].x[7]);
            rs10 += eterm(cf[1][ni].x[0]) + eterm(cf[1][ni].x[1])
                  + eterm(cf[1][ni].x[4]) + eterm(cf[1][ni].x[5]);
            rs11 += eterm(cf[1][ni].x[2]) + eterm(cf[1][ni].x[3])
                  + eterm(cf[1][ni].x[6]) + eterm(cf[1][ni].x[7]);
        }

        // Commit prefetched tile
        if (t + 1 < CTILES) {
            #pragma unroll
            for (int j = 0; j < 16; j++) {
                int idx = tid + j * 256;
                float* d = &Bn[(idx >> 5) * LDA + (idx & 31) * 4];
                d[0] = pre[j].x; d[1] = pre[j].y; d[2] = pre[j].z; d[3] = pre[j].w;
            }
        }
        __syncthreads();
    }

    // Quad reduction: lanes in a quad hold the same row.
    rs00 += __shfl_xor_sync(0xffffffffu, rs00, 1);
    rs00 += __shfl_xor_sync(0xffffffffu, rs00, 2);
    rs01 += __shfl_xor_sync(0xffffffffu, rs01, 1);
    rs01 += __shfl_xor_sync(0xffffffffu, rs01, 2);
    rs10 += __shfl_xor_sync(0xffffffffu, rs10, 1);
    rs10 += __shfl_xor_sync(0xffffffffu, rs10, 2);
    rs11 += __shfl_xor_sync(0xffffffffu, rs11, 1);
    rs11 += __shfl_xor_sync(0xffffffffu, rs11, 2);

    float* red = sm;   // reuse As region (all MMAs done)
    int g = lid >> 2;
    if ((lid & 3) == 0) {
        red[(wr * 32 + g) * 2 + wc]      = rs00;
        red[(wr * 32 + g + 8) * 2 + wc]  = rs01;
        red[(wr * 32 + 16 + g) * 2 + wc] = rs10;
        red[(wr * 32 + 24 + g) * 2 + wc] = rs11;
    }
    __syncthreads();
    if (tid < TM)
        atomicAdd(&g_rowsum[r0 + tid], red[tid * 2] + red[tid * 2 + 1]);  // 2 commutative adds/row
}

// loss = mean( log(rowsum - exp(self)) - pos )
__global__ void kfin(float* __restrict__ out) {
    int t = threadIdx.x;   // 1024
    float a = 0.0f;
    for (int i = t; i < NN; i += 1024)
        a += __logf(g_rowsum[i] - __expf(g_self[i])) - g_pos[i];
    #pragma unroll
    for (int o = 16; o > 0; o >>= 1) a += __shfl_xor_sync(0xffffffffu, a, o);
    __shared__ float ws[32];
    if ((t & 31) == 0) ws[t >> 5] = a;
    __syncthreads();
    if (t == 0) {
        float s = 0.0f;
        #pragma unroll
        for (int w = 0; w < 32; w++) s += ws[w];
        out[0] = s / (float)NN;
    }
}

extern "C" void kernel_launch(void* const* d_in, const int* in_sizes, int n_in,
                              void* d_out, int out_size) {
    const float* zi = (const float*)d_in[0];
    const float* zj = (const float*)d_in[1];
    float* out = (float*)d_out;
    (void)in_sizes; (void)n_in; (void)out_size;

    cudaFuncSetAttribute(kmain, cudaFuncAttributeMaxDynamicSharedMemorySize, SMEM_BYTES);

    kprep<<<NB, DD>>>(zi, zj);
    dim3 grid(NN / TM, NSPLIT);
    kmain<<<grid, 256, SMEM_BYTES>>>();
    kfin<<<1, 1024>>>(out);
}